// round 14
// baseline (speedup 1.0000x reference)
#include <cuda_runtime.h>
#include <cuda_bf16.h>
#include <cuda_fp16.h>
#include <cstdint>

// Problem constants
#define NB 16
#define CC 512
#define NN 2304      // 48*48
#define II 64        // inter channels

// tf32 mma tiling: 128x128 block, TBK=32 fp32 slabs, double-buffered
#define TBK 32
#define BKP 36                  // padded k-stride (uints / half2): mod 32 = 4 -> conflict-free
#define TILE_U (128 * BKP)      // 4608 words per tensor per buffer
#define SMEM_VO (4 * TILE_U * 4)    // 73728 B  (2 tensors x 2 buffers)
#define SMEM_QK (8 * TILE_U * 4)    // 147456 B (4 tensors hi/lo x 2 buffers)

// k_s 3xTF32: whole K=64 in one stage, 4 tensors (A/B x hi/lo)
#define SKP 68
#define STILE_U (128 * SKP)
#define SMEM_S (4 * STILE_U * 4)    // 139264 B

// ---------------------------------------------------------------------------
// Scratch (device globals: allocation-free per harness rules)
// ---------------------------------------------------------------------------
__device__ float  g_qk[(size_t)NB * 128 * NN];      // rows 0..63 = q, 64..127 = k (fp32)
__device__ __half g_v [(size_t)NB * CC  * NN];      // v projection (fp16)
__device__ float  g_s [(size_t)NB * NN  * NN];      // attention logits (fp32)
__device__ __half g_p [(size_t)NB * NN  * NN];      // softmax probs (fp16)

// ---------------------------------------------------------------------------
// mma helpers
// ---------------------------------------------------------------------------
__device__ __forceinline__ uint32_t f2tf32(float f) {
    uint32_t r;
    asm("cvt.rna.tf32.f32 %0, %1;" : "=r"(r) : "f"(f));
    return r;
}

__device__ __forceinline__ void mma_tf32(float c[4], const uint32_t a[4],
                                         const uint32_t b[2]) {
    asm volatile(
        "mma.sync.aligned.m16n8k8.row.col.f32.tf32.tf32.f32 "
        "{%0,%1,%2,%3}, {%4,%5,%6,%7}, {%8,%9}, {%0,%1,%2,%3};"
        : "+f"(c[0]), "+f"(c[1]), "+f"(c[2]), "+f"(c[3])
        : "r"(a[0]), "r"(a[1]), "r"(a[2]), "r"(a[3]),
          "r"(b[0]), "r"(b[1]));
}

__device__ __forceinline__ void mma_f16(float c[4], const uint32_t a[4],
                                        const uint32_t b[2]) {
    asm volatile(
        "mma.sync.aligned.m16n8k16.row.col.f32.f16.f16.f32 "
        "{%0,%1,%2,%3}, {%4,%5,%6,%7}, {%8,%9}, {%0,%1,%2,%3};"
        : "+f"(c[0]), "+f"(c[1]), "+f"(c[2]), "+f"(c[3])
        : "r"(a[0]), "r"(a[1]), "r"(a[2]), "r"(a[3]),
          "r"(b[0]), "r"(b[1]));
}

// tf32 stage: one TBK=32 fp32 slab resident in smem (word stride BKP).
// Warp tile 32(m) x 64(n) -> 2 m-frags x 8 n-frags.
__device__ __forceinline__ void mma_stage(const uint32_t* __restrict__ As,
                                          const uint32_t* __restrict__ Bs,
                                          float acc[2][8][4],
                                          int wm, int wn, int gid, int tig) {
#pragma unroll
    for (int ks = 0; ks < TBK; ks += 8) {
        uint32_t a[2][4], bf[8][2];
#pragma unroll
        for (int mf = 0; mf < 2; mf++) {
            int r = (wm * 32 + mf * 16 + gid) * BKP + ks + tig;
            a[mf][0] = As[r];
            a[mf][1] = As[r + 8 * BKP];
            a[mf][2] = As[r + 4];
            a[mf][3] = As[r + 8 * BKP + 4];
        }
#pragma unroll
        for (int nf = 0; nf < 8; nf++) {
            int r = (wn * 64 + nf * 8 + gid) * BKP + ks + tig;
            bf[nf][0] = Bs[r];
            bf[nf][1] = Bs[r + 4];
        }
#pragma unroll
        for (int mf = 0; mf < 2; mf++)
#pragma unroll
            for (int nf = 0; nf < 8; nf++)
                mma_tf32(acc[mf][nf], a[mf], bf[nf]);
    }
}

// f16 stage: one slab of K=64 halves (32 half2, word stride BKP=36 half2).
// Identical index math to mma_stage; each step is K=16 via m16n8k16.
__device__ __forceinline__ void mma_stage_f16(const uint32_t* __restrict__ As,
                                              const uint32_t* __restrict__ Bs,
                                              float acc[2][8][4],
                                              int wm, int wn, int gid, int tig) {
#pragma unroll
    for (int ks = 0; ks < 32; ks += 8) {
        uint32_t a[2][4], bf[8][2];
#pragma unroll
        for (int mf = 0; mf < 2; mf++) {
            int r = (wm * 32 + mf * 16 + gid) * BKP + ks + tig;
            a[mf][0] = As[r];
            a[mf][1] = As[r + 8 * BKP];
            a[mf][2] = As[r + 4];
            a[mf][3] = As[r + 8 * BKP + 4];
        }
#pragma unroll
        for (int nf = 0; nf < 8; nf++) {
            int r = (wn * 64 + nf * 8 + gid) * BKP + ks + tig;
            bf[nf][0] = Bs[r];
            bf[nf][1] = Bs[r + 4];
        }
#pragma unroll
        for (int mf = 0; mf < 2; mf++)
#pragma unroll
            for (int nf = 0; nf < 8; nf++)
                mma_f16(acc[mf][nf], a[mf], bf[nf]);
    }
}

// ---------------------------------------------------------------------------
// 1) q/k projection via 3xTF32 hi/lo (~fp32 accuracy on tensor pipe):
//    g_qk[b][i][n] = sum_c [Wq;Wk][i][c] * x[b][c][n]
//    grid (NN/128, 1, NB), 256 thr, K=512 loop, double-buffered hi/lo.
// ---------------------------------------------------------------------------
__global__ void __launch_bounds__(256)
k_qk(const float* __restrict__ x, const float* __restrict__ Wq,
     const float* __restrict__ Wk) {
    extern __shared__ __align__(16) uint32_t sm[];

    const int tid = threadIdx.x;
    const int n0 = blockIdx.x * 128;
    const int b  = blockIdx.z;

    const int lane = tid & 31;
    const int gid  = lane >> 2;
    const int tig  = lane & 3;
    const int warp = tid >> 5;
    const int wm   = warp >> 1;
    const int wn   = warp & 1;

    float acc[2][8][4];
#pragma unroll
    for (int mf = 0; mf < 2; mf++)
#pragma unroll
        for (int nf = 0; nf < 8; nf++)
#pragma unroll
            for (int i = 0; i < 4; i++) acc[mf][nf][i] = 0.f;

    const float* xb = x + (size_t)b * CC * NN;

    float4 ra[4];
    float  rb[16];

    auto load_tiles = [&](int k0) {
#pragma unroll
        for (int j = 0; j < 4; j++) {
            int t = tid + j * 256;
            int mm = t >> 3, k4 = (t & 7) << 2;
            const float* Wp = (mm < II) ? (Wq + (size_t)mm * CC)
                                        : (Wk + (size_t)(mm - II) * CC);
            ra[j] = *(const float4*)(Wp + k0 + k4);
        }
#pragma unroll
        for (int j = 0; j < 16; j++) {
            int t = tid + j * 256;
            int kk = t >> 7, nn = t & 127;
            rb[j] = xb[(size_t)(k0 + kk) * NN + n0 + nn];
        }
    };
    auto store_tiles = [&](int buf) {
        uint32_t* Ah = sm + buf * 4 * TILE_U;
        uint32_t* Al = Ah + TILE_U;
        uint32_t* Bh = Al + TILE_U;
        uint32_t* Bl = Bh + TILE_U;
#pragma unroll
        for (int j = 0; j < 4; j++) {
            int t = tid + j * 256;
            int mm = t >> 3, k4 = (t & 7) << 2;
            int idx = mm * BKP + k4;
            float f[4] = {ra[j].x, ra[j].y, ra[j].z, ra[j].w};
#pragma unroll
            for (int e = 0; e < 4; e++) {
                uint32_t h = f2tf32(f[e]);
                Ah[idx + e] = h;
                Al[idx + e] = f2tf32(f[e] - __uint_as_float(h));
            }
        }
#pragma unroll
        for (int j = 0; j < 16; j++) {
            int t = tid + j * 256;
            int kk = t >> 7, nn = t & 127;
            uint32_t h = f2tf32(rb[j]);
            Bh[nn * BKP + kk] = h;
            Bl[nn * BKP + kk] = f2tf32(rb[j] - __uint_as_float(h));
        }
    };

    load_tiles(0);
    store_tiles(0);
    __syncthreads();

    const int NIT = CC / TBK;   // 16
    for (int it = 0; it < NIT; it++) {
        int cur = it & 1;
        if (it + 1 < NIT) load_tiles((it + 1) * TBK);
        const uint32_t* base = sm + cur * 4 * TILE_U;
        mma_stage(base + TILE_U,     base + 2 * TILE_U, acc, wm, wn, gid, tig); // lo*hi
        mma_stage(base,              base + 3 * TILE_U, acc, wm, wn, gid, tig); // hi*lo
        mma_stage(base,              base + 2 * TILE_U, acc, wm, wn, gid, tig); // hi*hi
        if (it + 1 < NIT) store_tiles(cur ^ 1);
        __syncthreads();
    }

    float* outb = g_qk + (size_t)b * 128 * NN;
#pragma unroll
    for (int mf = 0; mf < 2; mf++)
#pragma unroll
        for (int nf = 0; nf < 8; nf++) {
            int r = wm * 32 + mf * 16 + gid;
            int n = n0 + wn * 64 + nf * 8 + tig * 2;
            size_t i0 = (size_t)r * NN + n;
            *(float2*)(outb + i0) = make_float2(acc[mf][nf][0], acc[mf][nf][1]);
            size_t i1 = i0 + (size_t)8 * NN;
            *(float2*)(outb + i1) = make_float2(acc[mf][nf][2], acc[mf][nf][3]);
        }
}

// ---------------------------------------------------------------------------
// 2) v projection (tf32, register-double-buffered), writes fp16:
//    g_v[b][o][n] = sum_c Wv[o][c] * x[b][c][n]
// ---------------------------------------------------------------------------
__global__ void __launch_bounds__(256)
k_v(const float* __restrict__ x, const float* __restrict__ Wv) {
    extern __shared__ __align__(16) uint32_t sm[];
    uint32_t* Asb = sm;
    uint32_t* Bsb = sm + 2 * TILE_U;

    const int tid = threadIdx.x;
    const int n0 = blockIdx.x * 128;
    const int m0 = blockIdx.y * 128;
    const int b  = blockIdx.z;

    const int lane = tid & 31;
    const int gid  = lane >> 2;
    const int tig  = lane & 3;
    const int warp = tid >> 5;
    const int wm   = warp >> 1;
    const int wn   = warp & 1;

    float acc[2][8][4];
#pragma unroll
    for (int mf = 0; mf < 2; mf++)
#pragma unroll
        for (int nf = 0; nf < 8; nf++)
#pragma unroll
            for (int i = 0; i < 4; i++) acc[mf][nf][i] = 0.f;

    const float* xb = x + (size_t)b * CC * NN;

    float4 ra[4];
    float  rb[16];

    auto load_tiles = [&](int k0) {
#pragma unroll
        for (int j = 0; j < 4; j++) {
            int t = tid + j * 256;
            int mm = t >> 3, k4 = (t & 7) << 2;
            ra[j] = *(const float4*)(Wv + (size_t)(m0 + mm) * CC + k0 + k4);
        }
#pragma unroll
        for (int j = 0; j < 16; j++) {
            int t = tid + j * 256;
            int kk = t >> 7, nn = t & 127;
            rb[j] = xb[(size_t)(k0 + kk) * NN + n0 + nn];
        }
    };
    auto store_tiles = [&](int buf) {
        uint32_t* As = Asb + buf * TILE_U;
        uint32_t* Bs = Bsb + buf * TILE_U;
#pragma unroll
        for (int j = 0; j < 4; j++) {
            int t = tid + j * 256;
            int mm = t >> 3, k4 = (t & 7) << 2;
            uint32_t* p = &As[mm * BKP + k4];
            p[0] = f2tf32(ra[j].x); p[1] = f2tf32(ra[j].y);
            p[2] = f2tf32(ra[j].z); p[3] = f2tf32(ra[j].w);
        }
#pragma unroll
        for (int j = 0; j < 16; j++) {
            int t = tid + j * 256;
            int kk = t >> 7, nn = t & 127;
            Bs[nn * BKP + kk] = f2tf32(rb[j]);
        }
    };

    load_tiles(0);
    store_tiles(0);
    __syncthreads();

    const int NIT = CC / TBK;   // 16
    for (int it = 0; it < NIT; it++) {
        int cur = it & 1;
        if (it + 1 < NIT) load_tiles((it + 1) * TBK);
        mma_stage(Asb + cur * TILE_U, Bsb + cur * TILE_U, acc, wm, wn, gid, tig);
        if (it + 1 < NIT) store_tiles(cur ^ 1);
        __syncthreads();
    }

    __half* outb = g_v + (size_t)b * CC * NN;
#pragma unroll
    for (int mf = 0; mf < 2; mf++)
#pragma unroll
        for (int nf = 0; nf < 8; nf++) {
            int o = m0 + wm * 32 + mf * 16 + gid;
            int n = n0 + wn * 64 + nf * 8 + tig * 2;
            size_t i0 = (size_t)o * NN + n;
            *(__half2*)(outb + i0) = __floats2half2_rn(acc[mf][nf][0], acc[mf][nf][1]);
            size_t i1 = i0 + (size_t)8 * NN;
            *(__half2*)(outb + i1) = __floats2half2_rn(acc[mf][nf][2], acc[mf][nf][3]);
        }
}

// ---------------------------------------------------------------------------
// 3) logits via 3xTF32 hi/lo, K=64 in one stage (fp32 out for softmax)
// ---------------------------------------------------------------------------
__global__ void __launch_bounds__(256)
k_s() {
    extern __shared__ __align__(16) uint32_t sm[];
    uint32_t* Ah = sm;
    uint32_t* Al = Ah + STILE_U;
    uint32_t* Bh = Al + STILE_U;
    uint32_t* Bl = Bh + STILE_U;

    const int tid = threadIdx.x;
    const int n0 = blockIdx.x * 128;     // key tile
    const int m0 = blockIdx.y * 128;     // query tile
    const int b  = blockIdx.z;

    const int lane = tid & 31;
    const int gid  = lane >> 2;
    const int tig  = lane & 3;
    const int warp = tid >> 5;
    const int wm   = warp >> 1;
    const int wn   = warp & 1;

    const float* qb = g_qk + (size_t)b * 128 * NN;
    const float* kb = qb + (size_t)II * NN;

    for (int t = tid; t < 128 * II; t += 256) {
        int mm = t & 127, kk = t >> 7;
        float f = qb[(size_t)kk * NN + m0 + mm];
        uint32_t h = f2tf32(f);
        Ah[mm * SKP + kk] = h;
        Al[mm * SKP + kk] = f2tf32(f - __uint_as_float(h));
    }
    for (int t = tid; t < 128 * II; t += 256) {
        int nn = t & 127, kk = t >> 7;
        float f = kb[(size_t)kk * NN + n0 + nn];
        uint32_t h = f2tf32(f);
        Bh[nn * SKP + kk] = h;
        Bl[nn * SKP + kk] = f2tf32(f - __uint_as_float(h));
    }
    __syncthreads();

    float acc[2][8][4];
#pragma unroll
    for (int mf = 0; mf < 2; mf++)
#pragma unroll
        for (int nf = 0; nf < 8; nf++)
#pragma unroll
            for (int i = 0; i < 4; i++) acc[mf][nf][i] = 0.f;

#pragma unroll
    for (int ks = 0; ks < II; ks += 8) {
        uint32_t ah[2][4], al[2][4], bh[8][2], bl[8][2];
#pragma unroll
        for (int mf = 0; mf < 2; mf++) {
            int r = (wm * 32 + mf * 16 + gid) * SKP + ks + tig;
            ah[mf][0] = Ah[r];            al[mf][0] = Al[r];
            ah[mf][1] = Ah[r + 8 * SKP];  al[mf][1] = Al[r + 8 * SKP];
            ah[mf][2] = Ah[r + 4];        al[mf][2] = Al[r + 4];
            ah[mf][3] = Ah[r + 8 * SKP + 4]; al[mf][3] = Al[r + 8 * SKP + 4];
        }
#pragma unroll
        for (int nf = 0; nf < 8; nf++) {
            int r = (wn * 64 + nf * 8 + gid) * SKP + ks + tig;
            bh[nf][0] = Bh[r];     bl[nf][0] = Bl[r];
            bh[nf][1] = Bh[r + 4]; bl[nf][1] = Bl[r + 4];
        }
#pragma unroll
        for (int mf = 0; mf < 2; mf++)
#pragma unroll
            for (int nf = 0; nf < 8; nf++) {
                mma_tf32(acc[mf][nf], al[mf], bh[nf]);
                mma_tf32(acc[mf][nf], ah[mf], bl[nf]);
                mma_tf32(acc[mf][nf], ah[mf], bh[nf]);
            }
    }

    float* sb = g_s + (size_t)b * NN * NN;
#pragma unroll
    for (int mf = 0; mf < 2; mf++)
#pragma unroll
        for (int nf = 0; nf < 8; nf++) {
            int qrow = m0 + wm * 32 + mf * 16 + gid;
            int kcol = n0 + wn * 64 + nf * 8 + tig * 2;
            size_t i0 = (size_t)qrow * NN + kcol;
            *(float2*)(sb + i0) = make_float2(acc[mf][nf][0], acc[mf][nf][1]);
            size_t i1 = i0 + (size_t)8 * NN;
            *(float2*)(sb + i1) = make_float2(acc[mf][nf][2], acc[mf][nf][3]);
        }
}

// ---------------------------------------------------------------------------
// 4) softmax: read fp32 logits, write fp16 probs (no fp32 writeback)
// ---------------------------------------------------------------------------
__global__ void __launch_bounds__(256)
k_softmax() {
    const int tid = threadIdx.x;
    const float* s = g_s + (size_t)blockIdx.x * NN;
    __half* p = g_p + (size_t)blockIdx.x * NN;

    float v[9];
    float mx = -1e30f;
#pragma unroll
    for (int j = 0; j < 9; j++) {
        v[j] = s[tid + j * 256];
        mx = fmaxf(mx, v[j]);
    }
#pragma unroll
    for (int o = 16; o > 0; o >>= 1)
        mx = fmaxf(mx, __shfl_xor_sync(0xFFFFFFFFu, mx, o));

    __shared__ float redm[8];
    __shared__ float reds[8];
    if ((tid & 31) == 0) redm[tid >> 5] = mx;
    __syncthreads();
    float m2 = redm[0];
#pragma unroll
    for (int w = 1; w < 8; w++) m2 = fmaxf(m2, redm[w]);

    float sum = 0.f;
#pragma unroll
    for (int j = 0; j < 9; j++) {
        v[j] = __expf(v[j] - m2);
        sum += v[j];
    }
#pragma unroll
    for (int o = 16; o > 0; o >>= 1)
        sum += __shfl_xor_sync(0xFFFFFFFFu, sum, o);
    if ((tid & 31) == 0) reds[tid >> 5] = sum;
    __syncthreads();
    float tot = 0.f;
#pragma unroll
    for (int w = 0; w < 8; w++) tot += reds[w];

    const float inv = 1.0f / tot;
#pragma unroll
    for (int j = 0; j < 9; j++)
        p[tid + j * 256] = __float2half_rn(v[j] * inv);
}

// ---------------------------------------------------------------------------
// 5) out GEMM (fp16 mma m16n8k16, register-double-buffered):
//    out[b][c][n] = gamma * sum_m v[b][c][m] * P[b][n][m] + x[b][c][n]
//    Operands already fp16 in gmem (g_v, g_p), K=64 halves per stage.
// ---------------------------------------------------------------------------
__global__ void __launch_bounds__(256)
k_out(const float* __restrict__ x, const float* __restrict__ gamma,
      float* __restrict__ out) {
    extern __shared__ __align__(16) uint32_t sm[];
    uint32_t* Asb = sm;
    uint32_t* Bsb = sm + 2 * TILE_U;

    const int tid = threadIdx.x;
    const int n0 = blockIdx.x * 128;
    const int c0 = blockIdx.y * 128;
    const int b  = blockIdx.z;

    const int lane = tid & 31;
    const int gid  = lane >> 2;
    const int tig  = lane & 3;
    const int warp = tid >> 5;
    const int wm   = warp >> 1;
    const int wn   = warp & 1;

    float acc[2][8][4];
#pragma unroll
    for (int mf = 0; mf < 2; mf++)
#pragma unroll
        for (int nf = 0; nf < 8; nf++)
#pragma unroll
            for (int i = 0; i < 4; i++) acc[mf][nf][i] = 0.f;

    const __half* vb = g_v + (size_t)b * CC * NN;
    const __half* pb = g_p + (size_t)b * NN * NN;

    uint4 ra[4], rb[4];

    auto load_tiles = [&](int k0) {   // k0 in halves, step 64
#pragma unroll
        for (int j = 0; j < 4; j++) {
            int t = tid + j * 256;
            int mm = t >> 3, k8 = (t & 7) << 3;   // 8-half granule
            ra[j] = *(const uint4*)(vb + (size_t)(c0 + mm) * NN + k0 + k8);
            rb[j] = *(const uint4*)(pb + (size_t)(n0 + mm) * NN + k0 + k8);
        }
    };
    auto store_tiles = [&](int buf) {
        uint32_t* As = Asb + buf * TILE_U;
        uint32_t* Bs = Bsb + buf * TILE_U;
#pragma unroll
        for (int j = 0; j < 4; j++) {
            int t = tid + j * 256;
            int mm = t >> 3, k4 = (t & 7) << 2;   // 4-half2 granule
            *(uint4*)&As[mm * BKP + k4] = ra[j];
            *(uint4*)&Bs[mm * BKP + k4] = rb[j];
        }
    };

    load_tiles(0);
    store_tiles(0);
    __syncthreads();

    const int NIT = NN / 64;    // 36
    for (int it = 0; it < NIT; it++) {
        int cur = it & 1;
        if (it + 1 < NIT) load_tiles((it + 1) * 64);
        mma_stage_f16(Asb + cur * TILE_U, Bsb + cur * TILE_U, acc, wm, wn, gid, tig);
        if (it + 1 < NIT) store_tiles(cur ^ 1);
        __syncthreads();
    }

    const float g = gamma[0];
    const float* xb = x + (size_t)b * CC * NN;
    float* ob = out + (size_t)b * CC * NN;
#pragma unroll
    for (int mf = 0; mf < 2; mf++)
#pragma unroll
        for (int nf = 0; nf < 8; nf++) {
            int c = c0 + wm * 32 + mf * 16 + gid;
            int n = n0 + wn * 64 + nf * 8 + tig * 2;
            size_t i0 = (size_t)c * NN + n;
            float2 x0 = *(const float2*)(xb + i0);
            *(float2*)(ob + i0) =
                make_float2(g * acc[mf][nf][0] + x0.x, g * acc[mf][nf][1] + x0.y);
            size_t i1 = i0 + (size_t)8 * NN;
            float2 x1 = *(const float2*)(xb + i1);
            *(float2*)(ob + i1) =
                make_float2(g * acc[mf][nf][2] + x1.x, g * acc[mf][nf][3] + x1.y);
        }
}

// ---------------------------------------------------------------------------
// Entry point: 5 sequential kernel launches, graph-capturable, no allocs.
// ---------------------------------------------------------------------------
extern "C" void kernel_launch(void* const* d_in, const int* in_sizes, int n_in,
                              void* d_out, int out_size) {
    const float* x     = (const float*)d_in[0];
    const float* Wq    = (const float*)d_in[1];
    const float* Wk    = (const float*)d_in[2];
    const float* Wv    = (const float*)d_in[3];
    const float* gamma = (const float*)d_in[4];
    float* out = (float*)d_out;

    cudaFuncSetAttribute(k_qk,  cudaFuncAttributeMaxDynamicSharedMemorySize, SMEM_QK);
    cudaFuncSetAttribute(k_v,   cudaFuncAttributeMaxDynamicSharedMemorySize, SMEM_VO);
    cudaFuncSetAttribute(k_s,   cudaFuncAttributeMaxDynamicSharedMemorySize, SMEM_S);
    cudaFuncSetAttribute(k_out, cudaFuncAttributeMaxDynamicSharedMemorySize, SMEM_VO);

    k_qk<<<dim3(NN / 128, 1, NB), 256, SMEM_QK>>>(x, Wq, Wk);
    k_v <<<dim3(NN / 128, CC / 128, NB), 256, SMEM_VO>>>(x, Wv);
    k_s <<<dim3(NN / 128, NN / 128, NB), 256, SMEM_S>>>();
    k_softmax<<<NB * NN, 256>>>();
    k_out<<<dim3(NN / 128, CC / 128, NB), 256, SMEM_VO>>>(x, gamma, out);
}

// round 16
// speedup vs baseline: 1.3039x; 1.3039x over previous
#include <cuda_runtime.h>
#include <cuda_bf16.h>
#include <cuda_fp16.h>
#include <cstdint>

// Problem constants
#define NB 16
#define CC 512
#define NN 2304      // 48*48
#define II 64        // inter channels

// fp32 SIMT tiling (k_qk)
#define BM 128
#define BN 128
#define BK 16
#define PAD 8

// fp16 mma tiling, K=64-half stages (k_s single stage, k_out)
#define BKP 36                    // half2-word k-stride: 36 mod 32 = 4 -> conflict-free frags
#define TILE_U (128 * BKP)        // 4608 words per tensor
#define SMEM_VO (4 * TILE_U * 4)  // k_out: 2 tensors x 2 buffers = 73728 B
#define SMEM_S16 (4 * TILE_U * 4) // k_s: 4 tensors (A/B x hi/lo), single stage = 73728 B

// fp16 mma tiling, K=32-half stages (k_v)
#define VKP 20                    // half2-word k-stride for 16-word rows
#define TILE_V (128 * VKP)        // 2560 words per tensor
#define SMEM_V (4 * TILE_V * 4)   // 2 tensors x 2 buffers = 40960 B

// ---------------------------------------------------------------------------
// Scratch (device globals: allocation-free per harness rules)
// ---------------------------------------------------------------------------
__device__ float  g_qk[(size_t)NB * 128 * NN];      // rows 0..63 = q, 64..127 = k (fp32)
__device__ __half g_v [(size_t)NB * CC  * NN];      // v projection (fp16)
__device__ float  g_s [(size_t)NB * NN  * NN];      // attention logits (fp32)
__device__ __half g_p [(size_t)NB * NN  * NN];      // softmax probs (fp16)

// ---------------------------------------------------------------------------
// mma helpers
// ---------------------------------------------------------------------------
__device__ __forceinline__ void mma_f16(float c[4], const uint32_t a[4],
                                        const uint32_t b[2]) {
    asm volatile(
        "mma.sync.aligned.m16n8k16.row.col.f32.f16.f16.f32 "
        "{%0,%1,%2,%3}, {%4,%5,%6,%7}, {%8,%9}, {%0,%1,%2,%3};"
        : "+f"(c[0]), "+f"(c[1]), "+f"(c[2]), "+f"(c[3])
        : "r"(a[0]), "r"(a[1]), "r"(a[2]), "r"(a[3]),
          "r"(b[0]), "r"(b[1]));
}

__device__ __forceinline__ uint32_t pack_h2(float x, float y) {
    __half2 h = __floats2half2_rn(x, y);
    return *reinterpret_cast<uint32_t*>(&h);
}

// f16 stage over K=64 halves (32 half2 words, stride BKP=36).
// Warp tile 32(m) x 64(n) -> 2 m-frags x 8 n-frags, K=16 per mma.
__device__ __forceinline__ void mma_stage_f16(const uint32_t* __restrict__ As,
                                              const uint32_t* __restrict__ Bs,
                                              float acc[2][8][4],
                                              int wm, int wn, int gid, int tig) {
#pragma unroll
    for (int ks = 0; ks < 32; ks += 8) {
        uint32_t a[2][4], bf[8][2];
#pragma unroll
        for (int mf = 0; mf < 2; mf++) {
            int r = (wm * 32 + mf * 16 + gid) * BKP + ks + tig;
            a[mf][0] = As[r];
            a[mf][1] = As[r + 8 * BKP];
            a[mf][2] = As[r + 4];
            a[mf][3] = As[r + 8 * BKP + 4];
        }
#pragma unroll
        for (int nf = 0; nf < 8; nf++) {
            int r = (wn * 64 + nf * 8 + gid) * BKP + ks + tig;
            bf[nf][0] = Bs[r];
            bf[nf][1] = Bs[r + 4];
        }
#pragma unroll
        for (int mf = 0; mf < 2; mf++)
#pragma unroll
            for (int nf = 0; nf < 8; nf++)
                mma_f16(acc[mf][nf], a[mf], bf[nf]);
    }
}

// f16 stage over K=32 halves (16 half2 words, stride VKP=20) — k_v.
__device__ __forceinline__ void mma_stage_f16_k32(const uint32_t* __restrict__ As,
                                                  const uint32_t* __restrict__ Bs,
                                                  float acc[2][8][4],
                                                  int wm, int wn, int gid, int tig) {
#pragma unroll
    for (int ks = 0; ks < 16; ks += 8) {
        uint32_t a[2][4], bf[8][2];
#pragma unroll
        for (int mf = 0; mf < 2; mf++) {
            int r = (wm * 32 + mf * 16 + gid) * VKP + ks + tig;
            a[mf][0] = As[r];
            a[mf][1] = As[r + 8 * VKP];
            a[mf][2] = As[r + 4];
            a[mf][3] = As[r + 8 * VKP + 4];
        }
#pragma unroll
        for (int nf = 0; nf < 8; nf++) {
            int r = (wn * 64 + nf * 8 + gid) * VKP + ks + tig;
            bf[nf][0] = Bs[r];
            bf[nf][1] = Bs[r + 4];
        }
#pragma unroll
        for (int mf = 0; mf < 2; mf++)
#pragma unroll
            for (int nf = 0; nf < 8; nf++)
                mma_f16(acc[mf][nf], a[mf], bf[nf]);
    }
}

// ---------------------------------------------------------------------------
// fp32 8x8-microtile compute stage (k_qk)
// ---------------------------------------------------------------------------
__device__ __forceinline__ void mm_compute(const float (*As)[BM + PAD],
                                           const float (*Bs)[BN + PAD],
                                           float acc[8][8], int tr, int tc) {
#pragma unroll
    for (int kk = 0; kk < BK; kk++) {
        float ra[8], rb[8];
#pragma unroll
        for (int r = 0; r < 8; r++) ra[r] = As[kk][tr * 8 + r];
#pragma unroll
        for (int c = 0; c < 8; c++) rb[c] = Bs[kk][tc * 8 + c];
#pragma unroll
        for (int r = 0; r < 8; r++)
#pragma unroll
            for (int c = 0; c < 8; c++)
                acc[r][c] += ra[r] * rb[c];
    }
}

// ---------------------------------------------------------------------------
// 1) q/k projection (fp32 SIMT — exact, feeds the softmax-sensitive path)
// ---------------------------------------------------------------------------
__global__ void __launch_bounds__(256)
k_qk(const float* __restrict__ x, const float* __restrict__ Wq,
     const float* __restrict__ Wk) {
    __shared__ float As[BK][BM + PAD];
    __shared__ float Bs[BK][BN + PAD];

    const int tid = threadIdx.x;
    const int n0 = blockIdx.x * BN;
    const int b  = blockIdx.z;
    const int tr = tid / 16, tc = tid % 16;

    float acc[8][8];
#pragma unroll
    for (int r = 0; r < 8; r++)
#pragma unroll
        for (int c = 0; c < 8; c++) acc[r][c] = 0.f;

    const float* xb = x + (size_t)b * CC * NN;

    for (int k0 = 0; k0 < CC; k0 += BK) {
        for (int i = tid; i < BM * BK; i += 256) {
            int mm = i / BK, kk = i % BK;
            const float* Wp = (mm < II) ? (Wq + (size_t)mm * CC)
                                        : (Wk + (size_t)(mm - II) * CC);
            As[kk][mm] = Wp[k0 + kk];
        }
        for (int i = tid; i < BK * BN; i += 256) {
            int kk = i / BN, nn = i % BN;
            Bs[kk][nn] = xb[(size_t)(k0 + kk) * NN + n0 + nn];
        }
        __syncthreads();
        mm_compute(As, Bs, acc, tr, tc);
        __syncthreads();
    }

    float* outb = g_qk + (size_t)b * 128 * NN;
#pragma unroll
    for (int r = 0; r < 8; r++) {
        size_t base = (size_t)(tr * 8 + r) * NN + n0 + tc * 8;
        *(float4*)(outb + base)     = make_float4(acc[r][0], acc[r][1], acc[r][2], acc[r][3]);
        *(float4*)(outb + base + 4) = make_float4(acc[r][4], acc[r][5], acc[r][6], acc[r][7]);
    }
}

// ---------------------------------------------------------------------------
// 2) v projection (single-pass fp16 mma — same 10-bit mantissa as tf32):
//    g_v[b][o][n] = sum_c Wv[o][c] * x[b][c][n].  K=32-half stages, double-buf.
// ---------------------------------------------------------------------------
__global__ void __launch_bounds__(256)
k_v(const float* __restrict__ x, const float* __restrict__ Wv) {
    extern __shared__ __align__(16) uint32_t sm[];
    uint32_t* Asb = sm;                  // [2][TILE_V]
    uint32_t* Bsb = sm + 2 * TILE_V;

    const int tid = threadIdx.x;
    const int n0 = blockIdx.x * 128;
    const int m0 = blockIdx.y * 128;
    const int b  = blockIdx.z;

    const int lane = tid & 31;
    const int gid  = lane >> 2;
    const int tig  = lane & 3;
    const int warp = tid >> 5;
    const int wm   = warp >> 1;
    const int wn   = warp & 1;

    float acc[2][8][4];
#pragma unroll
    for (int mf = 0; mf < 2; mf++)
#pragma unroll
        for (int nf = 0; nf < 8; nf++)
#pragma unroll
            for (int i = 0; i < 4; i++) acc[mf][nf][i] = 0.f;

    const float* xb = x + (size_t)b * CC * NN;

    uint32_t rah[8];   // A: 4 float4 -> 8 half2 words
    uint32_t rbh[8];   // B: 8 k-pair units -> 8 half2 words

    auto load_tiles = [&](int k0) {
        // A = Wv rows: 128 x 32 floats = 1024 float4; 4 per thread
#pragma unroll
        for (int j = 0; j < 4; j++) {
            int t = tid + j * 256;
            int mm = t >> 3, kf = (t & 7) << 2;
            float4 f = *(const float4*)(Wv + (size_t)(m0 + mm) * CC + k0 + kf);
            rah[j * 2]     = pack_h2(f.x, f.y);
            rah[j * 2 + 1] = pack_h2(f.z, f.w);
        }
        // B = x transposed pairs: kk2 in [0,16), nn in [0,128); 8 units/thread
#pragma unroll
        for (int j = 0; j < 8; j++) {
            int t = tid + j * 256;
            int kk2 = t >> 7, nn = t & 127;
            float f0 = xb[(size_t)(k0 + 2 * kk2) * NN + n0 + nn];
            float f1 = xb[(size_t)(k0 + 2 * kk2 + 1) * NN + n0 + nn];
            rbh[j] = pack_h2(f0, f1);
        }
    };
    auto store_tiles = [&](int buf) {
        uint32_t* As = Asb + buf * TILE_V;
        uint32_t* Bs = Bsb + buf * TILE_V;
#pragma unroll
        for (int j = 0; j < 4; j++) {
            int t = tid + j * 256;
            int mm = t >> 3, kw = (t & 7) << 1;   // half2-word offset
            As[mm * VKP + kw]     = rah[j * 2];
            As[mm * VKP + kw + 1] = rah[j * 2 + 1];
        }
#pragma unroll
        for (int j = 0; j < 8; j++) {
            int t = tid + j * 256;
            int kk2 = t >> 7, nn = t & 127;
            Bs[nn * VKP + kk2] = rbh[j];
        }
    };

    load_tiles(0);
    store_tiles(0);
    __syncthreads();

    const int NIT = CC / 32;   // 16
    for (int it = 0; it < NIT; it++) {
        int cur = it & 1;
        if (it + 1 < NIT) load_tiles((it + 1) * 32);
        mma_stage_f16_k32(Asb + cur * TILE_V, Bsb + cur * TILE_V, acc, wm, wn, gid, tig);
        if (it + 1 < NIT) store_tiles(cur ^ 1);
        __syncthreads();
    }

    __half* outb = g_v + (size_t)b * CC * NN;
#pragma unroll
    for (int mf = 0; mf < 2; mf++)
#pragma unroll
        for (int nf = 0; nf < 8; nf++) {
            int o = m0 + wm * 32 + mf * 16 + gid;
            int n = n0 + wn * 64 + nf * 8 + tig * 2;
            size_t i0 = (size_t)o * NN + n;
            *(__half2*)(outb + i0) = __floats2half2_rn(acc[mf][nf][0], acc[mf][nf][1]);
            size_t i1 = i0 + (size_t)8 * NN;
            *(__half2*)(outb + i1) = __floats2half2_rn(acc[mf][nf][2], acc[mf][nf][3]);
        }
}

// ---------------------------------------------------------------------------
// 3) logits via 3x fp16 hi/lo split (error ~2^-22 per product, safe for softmax):
//    g_s[b][n][m] = sum_i q[b][i][n] * k[b][i][m].  K=64 in one smem stage.
// ---------------------------------------------------------------------------
__global__ void __launch_bounds__(256)
k_s() {
    extern __shared__ __align__(16) uint32_t sm[];
    uint32_t* Ah = sm;                   // query hi  [128][BKP]
    uint32_t* Al = Ah + TILE_U;          // query lo
    uint32_t* Bh = Al + TILE_U;          // key hi
    uint32_t* Bl = Bh + TILE_U;          // key lo

    const int tid = threadIdx.x;
    const int n0 = blockIdx.x * 128;     // key tile
    const int m0 = blockIdx.y * 128;     // query tile
    const int b  = blockIdx.z;

    const int lane = tid & 31;
    const int gid  = lane >> 2;
    const int tig  = lane & 3;
    const int warp = tid >> 5;
    const int wm   = warp >> 1;
    const int wn   = warp & 1;

    const float* qb = g_qk + (size_t)b * 128 * NN;   // rows [0,64): q
    const float* kb = qb + (size_t)II * NN;          // rows [64,128): k

    // kk2 in [0,32) k-pairs, mm/nn in [0,128)
    for (int t = tid; t < 32 * 128; t += 256) {
        int kk2 = t >> 7, mm = t & 127;
        float f0 = qb[(size_t)(2 * kk2) * NN + m0 + mm];
        float f1 = qb[(size_t)(2 * kk2 + 1) * NN + m0 + mm];
        __half h0 = __float2half_rn(f0), h1 = __float2half_rn(f1);
        __half2 hh = __halves2half2(h0, h1);
        __half2 ll = __floats2half2_rn(f0 - __half2float(h0), f1 - __half2float(h1));
        Ah[mm * BKP + kk2] = *reinterpret_cast<uint32_t*>(&hh);
        Al[mm * BKP + kk2] = *reinterpret_cast<uint32_t*>(&ll);
    }
    for (int t = tid; t < 32 * 128; t += 256) {
        int kk2 = t >> 7, nn = t & 127;
        float f0 = kb[(size_t)(2 * kk2) * NN + n0 + nn];
        float f1 = kb[(size_t)(2 * kk2 + 1) * NN + n0 + nn];
        __half h0 = __float2half_rn(f0), h1 = __float2half_rn(f1);
        __half2 hh = __halves2half2(h0, h1);
        __half2 ll = __floats2half2_rn(f0 - __half2float(h0), f1 - __half2float(h1));
        Bh[nn * BKP + kk2] = *reinterpret_cast<uint32_t*>(&hh);
        Bl[nn * BKP + kk2] = *reinterpret_cast<uint32_t*>(&ll);
    }
    __syncthreads();

    float acc[2][8][4];
#pragma unroll
    for (int mf = 0; mf < 2; mf++)
#pragma unroll
        for (int nf = 0; nf < 8; nf++)
#pragma unroll
            for (int i = 0; i < 4; i++) acc[mf][nf][i] = 0.f;

    mma_stage_f16(Ah, Bh, acc, wm, wn, gid, tig);   // hi*hi
    mma_stage_f16(Ah, Bl, acc, wm, wn, gid, tig);   // hi*lo
    mma_stage_f16(Al, Bh, acc, wm, wn, gid, tig);   // lo*hi

    float* sb = g_s + (size_t)b * NN * NN;
#pragma unroll
    for (int mf = 0; mf < 2; mf++)
#pragma unroll
        for (int nf = 0; nf < 8; nf++) {
            int qrow = m0 + wm * 32 + mf * 16 + gid;
            int kcol = n0 + wn * 64 + nf * 8 + tig * 2;
            size_t i0 = (size_t)qrow * NN + kcol;
            *(float2*)(sb + i0) = make_float2(acc[mf][nf][0], acc[mf][nf][1]);
            size_t i1 = i0 + (size_t)8 * NN;
            *(float2*)(sb + i1) = make_float2(acc[mf][nf][2], acc[mf][nf][3]);
        }
}

// ---------------------------------------------------------------------------
// 4) softmax: read fp32 logits, write fp16 probs
// ---------------------------------------------------------------------------
__global__ void __launch_bounds__(256)
k_softmax() {
    const int tid = threadIdx.x;
    const float* s = g_s + (size_t)blockIdx.x * NN;
    __half* p = g_p + (size_t)blockIdx.x * NN;

    float v[9];
    float mx = -1e30f;
#pragma unroll
    for (int j = 0; j < 9; j++) {
        v[j] = s[tid + j * 256];
        mx = fmaxf(mx, v[j]);
    }
#pragma unroll
    for (int o = 16; o > 0; o >>= 1)
        mx = fmaxf(mx, __shfl_xor_sync(0xFFFFFFFFu, mx, o));

    __shared__ float redm[8];
    __shared__ float reds[8];
    if ((tid & 31) == 0) redm[tid >> 5] = mx;
    __syncthreads();
    float m2 = redm[0];
#pragma unroll
    for (int w = 1; w < 8; w++) m2 = fmaxf(m2, redm[w]);

    float sum = 0.f;
#pragma unroll
    for (int j = 0; j < 9; j++) {
        v[j] = __expf(v[j] - m2);
        sum += v[j];
    }
#pragma unroll
    for (int o = 16; o > 0; o >>= 1)
        sum += __shfl_xor_sync(0xFFFFFFFFu, sum, o);
    if ((tid & 31) == 0) reds[tid >> 5] = sum;
    __syncthreads();
    float tot = 0.f;
#pragma unroll
    for (int w = 0; w < 8; w++) tot += reds[w];

    const float inv = 1.0f / tot;
#pragma unroll
    for (int j = 0; j < 9; j++)
        p[tid + j * 256] = __float2half_rn(v[j] * inv);
}

// ---------------------------------------------------------------------------
// 5) out GEMM (fp16 mma m16n8k16, register-double-buffered):
//    out[b][c][n] = gamma * sum_m v[b][c][m] * P[b][n][m] + x[b][c][n]
// ---------------------------------------------------------------------------
__global__ void __launch_bounds__(256)
k_out(const float* __restrict__ x, const float* __restrict__ gamma,
      float* __restrict__ out) {
    extern __shared__ __align__(16) uint32_t sm[];
    uint32_t* Asb = sm;
    uint32_t* Bsb = sm + 2 * TILE_U;

    const int tid = threadIdx.x;
    const int n0 = blockIdx.x * 128;
    const int c0 = blockIdx.y * 128;
    const int b  = blockIdx.z;

    const int lane = tid & 31;
    const int gid  = lane >> 2;
    const int tig  = lane & 3;
    const int warp = tid >> 5;
    const int wm   = warp >> 1;
    const int wn   = warp & 1;

    float acc[2][8][4];
#pragma unroll
    for (int mf = 0; mf < 2; mf++)
#pragma unroll
        for (int nf = 0; nf < 8; nf++)
#pragma unroll
            for (int i = 0; i < 4; i++) acc[mf][nf][i] = 0.f;

    const __half* vb = g_v + (size_t)b * CC * NN;
    const __half* pb = g_p + (size_t)b * NN * NN;

    uint4 ra[4], rb[4];

    auto load_tiles = [&](int k0) {   // k0 in halves, step 64
#pragma unroll
        for (int j = 0; j < 4; j++) {
            int t = tid + j * 256;
            int mm = t >> 3, k8 = (t & 7) << 3;
            ra[j] = *(const uint4*)(vb + (size_t)(c0 + mm) * NN + k0 + k8);
            rb[j] = *(const uint4*)(pb + (size_t)(n0 + mm) * NN + k0 + k8);
        }
    };
    auto store_tiles = [&](int buf) {
        uint32_t* As = Asb + buf * TILE_U;
        uint32_t* Bs = Bsb + buf * TILE_U;
#pragma unroll
        for (int j = 0; j < 4; j++) {
            int t = tid + j * 256;
            int mm = t >> 3, k4 = (t & 7) << 2;
            *(uint4*)&As[mm * BKP + k4] = ra[j];
            *(uint4*)&Bs[mm * BKP + k4] = rb[j];
        }
    };

    load_tiles(0);
    store_tiles(0);
    __syncthreads();

    const int NIT = NN / 64;    // 36
    for (int it = 0; it < NIT; it++) {
        int cur = it & 1;
        if (it + 1 < NIT) load_tiles((it + 1) * 64);
        mma_stage_f16(Asb + cur * TILE_U, Bsb + cur * TILE_U, acc, wm, wn, gid, tig);
        if (it + 1 < NIT) store_tiles(cur ^ 1);
        __syncthreads();
    }

    const float g = gamma[0];
    const float* xb = x + (size_t)b * CC * NN;
    float* ob = out + (size_t)b * CC * NN;
#pragma unroll
    for (int mf = 0; mf < 2; mf++)
#pragma unroll
        for (int nf = 0; nf < 8; nf++) {
            int c = c0 + wm * 32 + mf * 16 + gid;
            int n = n0 + wn * 64 + nf * 8 + tig * 2;
            size_t i0 = (size_t)c * NN + n;
            float2 x0 = *(const float2*)(xb + i0);
            *(float2*)(ob + i0) =
                make_float2(g * acc[mf][nf][0] + x0.x, g * acc[mf][nf][1] + x0.y);
            size_t i1 = i0 + (size_t)8 * NN;
            float2 x1 = *(const float2*)(xb + i1);
            *(float2*)(ob + i1) =
                make_float2(g * acc[mf][nf][2] + x1.x, g * acc[mf][nf][3] + x1.y);
        }
}

// ---------------------------------------------------------------------------
// Entry point: 5 sequential kernel launches, graph-capturable, no allocs.
// ---------------------------------------------------------------------------
extern "C" void kernel_launch(void* const* d_in, const int* in_sizes, int n_in,
                              void* d_out, int out_size) {
    const float* x     = (const float*)d_in[0];
    const float* Wq    = (const float*)d_in[1];
    const float* Wk    = (const float*)d_in[2];
    const float* Wv    = (const float*)d_in[3];
    const float* gamma = (const float*)d_in[4];
    float* out = (float*)d_out;

    cudaFuncSetAttribute(k_v,   cudaFuncAttributeMaxDynamicSharedMemorySize, SMEM_V);
    cudaFuncSetAttribute(k_s,   cudaFuncAttributeMaxDynamicSharedMemorySize, SMEM_S16);
    cudaFuncSetAttribute(k_out, cudaFuncAttributeMaxDynamicSharedMemorySize, SMEM_VO);

    k_qk<<<dim3(NN / BN, 1, NB), 256>>>(x, Wq, Wk);
    k_v <<<dim3(NN / 128, CC / 128, NB), 256, SMEM_V>>>(x, Wv);
    k_s <<<dim3(NN / 128, NN / 128, NB), 256, SMEM_S16>>>();
    k_softmax<<<NB * NN, 256>>>();
    k_out<<<dim3(NN / 128, CC / 128, NB), 256, SMEM_VO>>>(x, gamma, out);
}